// round 2
// baseline (speedup 1.0000x reference)
#include <cuda_runtime.h>
#include <cuda_bf16.h>
#include <cstdint>

#define NPTS 8192
#define DIM  512
#define MARGINF 0.3f

#define BM 128
#define BN 128
#define BK 64                    // bf16 elems per K chunk (128 B per row)
#define NCHUNK (DIM/BK)          // 8
#define GB (NPTS/BM)             // 64 tile-blocks per side
#define NPART (GB*(GB+1)/2)      // 2080 upper-triangular tiles

#define STAGES 3
#define STAGE_BYTES 32768        // 16KB A + 16KB B
#define SMEM_BYTES (1024 + STAGES*STAGE_BYTES)

// ---------------- device scratch (no allocations allowed) ----------------
__device__ __nv_bfloat16 g_X[NPTS*DIM];   // 8 MB bf16 copy of inputs
__device__ int   g_lab[NPTS];
__device__ float g_part[NPART];

// ---------------- helpers ----------------
__device__ __forceinline__ uint32_t smem_u32(const void* p){
    uint32_t a;
    asm("{ .reg .u64 t; cvta.to.shared.u64 t, %1; cvt.u32.u64 %0, t; }"
        : "=r"(a) : "l"(p));
    return a;
}
#define SW128(o) ((o) ^ (((o) >> 3) & 0x70))

__device__ __forceinline__ void cp16(uint32_t s, const void* g){
    asm volatile("cp.async.cg.shared.global [%0], [%1], 16;" :: "r"(s), "l"(g));
}
#define CP_COMMIT() asm volatile("cp.async.commit_group;" ::: "memory")
#define CP_WAIT(n)  asm volatile("cp.async.wait_group %0;" :: "n"(n) : "memory")

__device__ __forceinline__ void ldm_x4(uint32_t* r, uint32_t addr){
    asm volatile("ldmatrix.sync.aligned.m8n8.x4.shared.b16 {%0,%1,%2,%3}, [%4];"
                 : "=r"(r[0]), "=r"(r[1]), "=r"(r[2]), "=r"(r[3]) : "r"(addr));
}
__device__ __forceinline__ void mma16816(float* d, const uint32_t* a,
                                         uint32_t b0, uint32_t b1){
    asm volatile(
        "mma.sync.aligned.m16n8k16.row.col.f32.bf16.bf16.f32 "
        "{%0,%1,%2,%3}, {%4,%5,%6,%7}, {%8,%9}, {%0,%1,%2,%3};"
        : "+f"(d[0]), "+f"(d[1]), "+f"(d[2]), "+f"(d[3])
        : "r"(a[0]), "r"(a[1]), "r"(a[2]), "r"(a[3]), "r"(b0), "r"(b1));
}

// ---------------- kernel 1: convert inputs to bf16 + normalize labels ----------------
__global__ void prep_kernel(const float* __restrict__ x, const void* __restrict__ tgt){
    int idx = blockIdx.x * blockDim.x + threadIdx.x;   // NPTS*DIM/4 threads
    const float4 v = ((const float4*)x)[idx];
    __nv_bfloat16* o = g_X + (size_t)idx * 4;
    o[0] = __float2bfloat16(v.x);
    o[1] = __float2bfloat16(v.y);
    o[2] = __float2bfloat16(v.z);
    o[3] = __float2bfloat16(v.w);

    if (blockIdx.x == 0){
        // detect int64 vs int32 labels: values in [0,128); if int64, all odd words are 0
        const int* w = (const int*)tgt;
        bool is64 = true;
        #pragma unroll 1
        for (int k = 0; k < 64; k++)
            if (w[2*k + 1] != 0) { is64 = false; break; }
        if (is64){
            const long long* t64 = (const long long*)tgt;
            for (int i = threadIdx.x; i < NPTS; i += blockDim.x)
                g_lab[i] = (int)t64[i];
        } else {
            for (int i = threadIdx.x; i < NPTS; i += blockDim.x)
                g_lab[i] = w[i];
        }
    }
}

// ---------------- kernel 2: HMMA GEMM (upper-tri tiles) + fused masked loss ----------------
__global__ void __launch_bounds__(256, 2) contrastive_gemm(){
    extern __shared__ char smem[];
    const uint32_t sb = smem_u32(smem);
    const int tid = threadIdx.x;
    const int wid = tid >> 5, lane = tid & 31;

    // map blockIdx.x -> upper-triangular (bi, bj), bi <= bj
    int bi = 0, rem = blockIdx.x;
    while (rem >= GB - bi){ rem -= GB - bi; bi++; }
    const int bj = bi + rem;
    const int i0 = bi * BM, j0 = bj * BN;
    const bool diag = (bi == bj);

    // labels into smem
    int* ilab = (int*)smem;            // 128 ints
    int* jlab = ilab + 128;            // 128 ints
    if (tid < 128)        ilab[tid]       = g_lab[i0 + tid];
    else                  jlab[tid - 128] = g_lab[j0 + (tid - 128)];

    // cp.async tile loader: thread -> (row r + {0,32,64,96}, 16B chunk v)
    const int rr = tid >> 3, vv = tid & 7;
    auto load_stage = [&](int c){
        const uint32_t sA = sb + 1024 + (c % STAGES) * STAGE_BYTES;
        const uint32_t sB = sA + 16384;
        const int kc = c * BK;
        #pragma unroll
        for (int p = 0; p < 4; p++){
            const int r = rr + p * 32;
            cp16(sA + SW128(r * 128 + vv * 16),
                 g_X + (size_t)(i0 + r) * DIM + kc + vv * 8);
            cp16(sB + SW128(r * 128 + vv * 16),
                 g_X + (size_t)(j0 + r) * DIM + kc + vv * 8);
        }
    };

    load_stage(0); CP_COMMIT();
    load_stage(1); CP_COMMIT();

    const int wm0 = (wid & 3) * 32;     // warp row base   (4 warps in M)
    const int wn0 = (wid >> 2) * 64;    // warp col base   (2 warps in N)

    float acc[2][8][4];
    #pragma unroll
    for (int tm = 0; tm < 2; tm++)
        #pragma unroll
        for (int tn = 0; tn < 8; tn++)
            #pragma unroll
            for (int e = 0; e < 4; e++) acc[tm][tn][e] = 0.f;

    const int lrow = lane & 15, lhi = lane >> 4;

    for (int c = 0; c < NCHUNK; c++){
        CP_WAIT(1);
        __syncthreads();
        if (c + 2 < NCHUNK) load_stage(c + 2);
        CP_COMMIT();

        const uint32_t sA = sb + 1024 + (c % STAGES) * STAGE_BYTES;
        const uint32_t sB = sA + 16384;
        #pragma unroll
        for (int ks = 0; ks < 4; ks++){
            const int cb = ks * 32 + lhi * 16;
            uint32_t a[2][4];
            #pragma unroll
            for (int tm = 0; tm < 2; tm++)
                ldm_x4(a[tm], sA + SW128((wm0 + tm * 16 + lrow) * 128 + cb));
            uint32_t b[4][4];
            #pragma unroll
            for (int tp = 0; tp < 4; tp++)
                ldm_x4(b[tp], sB + SW128((wn0 + tp * 16 + lrow) * 128 + cb));
            #pragma unroll
            for (int tm = 0; tm < 2; tm++)
                #pragma unroll
                for (int tp = 0; tp < 4; tp++){
                    mma16816(acc[tm][2*tp],     a[tm], b[tp][0], b[tp][2]);
                    mma16816(acc[tm][2*tp + 1], a[tm], b[tp][1], b[tp][3]);
                }
        }
        __syncthreads();
    }

    // ---------------- fused masked loss on register accumulators ----------------
    const int r0 = lane >> 2, c0 = (lane & 3) * 2;
    float loss = 0.f;
    #pragma unroll
    for (int tm = 0; tm < 2; tm++){
        const int rowA = wm0 + tm * 16 + r0;
        const int liA  = ilab[rowA];
        const int liB  = ilab[rowA + 8];
        #pragma unroll
        for (int tn = 0; tn < 8; tn++){
            const int colb = wn0 + tn * 8 + c0;
            const int lj0 = jlab[colb], lj1 = jlab[colb + 1];
            #pragma unroll
            for (int e = 0; e < 4; e++){
                const float v = acc[tm][tn][e];
                const int row = (e >> 1) ? rowA + 8 : rowA;
                const int li  = (e >> 1) ? liB : liA;
                const int lj  = (e & 1) ? lj1 : lj0;
                float w = 2.f;
                if (diag){
                    const int gi = row, gj = colb + (e & 1);
                    w = (gi < gj) ? 2.f : ((gi == gj) ? 1.f : 0.f);
                }
                float l;
                if (li == lj) l = (v < 1.f) ? (1.f - v) : 0.f;
                else          l = (v > MARGINF) ? v : 0.f;
                loss += w * l;
            }
        }
    }

    // block reduction -> per-tile partial
    #pragma unroll
    for (int o = 16; o; o >>= 1) loss += __shfl_xor_sync(0xffffffffu, loss, o);
    __syncthreads();                      // labels no longer needed
    float* wsum = (float*)smem;
    if (lane == 0) wsum[wid] = loss;
    __syncthreads();
    if (tid == 0){
        float s = 0.f;
        #pragma unroll
        for (int w = 0; w < 8; w++) s += wsum[w];
        g_part[blockIdx.x] = s;
    }
}

// ---------------- kernel 3: deterministic final reduction ----------------
__global__ void reduce_kernel(float* __restrict__ out){
    __shared__ float sm[512];
    const int t = threadIdx.x;
    float v = 0.f;
    for (int i = t; i < NPART; i += 512) v += g_part[i];
    sm[t] = v;
    __syncthreads();
    for (int s = 256; s > 0; s >>= 1){
        if (t < s) sm[t] += sm[t + s];
        __syncthreads();
    }
    if (t == 0) out[0] = sm[0] / (float)NPTS;
}

// ---------------- launch ----------------
extern "C" void kernel_launch(void* const* d_in, const int* in_sizes, int n_in,
                              void* d_out, int out_size){
    const float* x   = (const float*)d_in[0];
    const void*  tgt = d_in[1];
    float* out = (float*)d_out;

    cudaFuncSetAttribute(contrastive_gemm,
                         cudaFuncAttributeMaxDynamicSharedMemorySize, SMEM_BYTES);

    prep_kernel<<<NPTS*DIM/1024, 256>>>(x, tgt);
    contrastive_gemm<<<NPART, 256, SMEM_BYTES>>>();
    reduce_kernel<<<1, 512>>>(out);
}